// round 14
// baseline (speedup 1.0000x reference)
#include <cuda_runtime.h>
#include <cuda_bf16.h>

// SAN Subtraction: out[n,c,kk,p] = x[n,c,h,w] - reflectpad(x)[n,c,h+kh,w+kw]
// N=4, C=64, H=W=112, K=7, PAD=3, reflect. out (N,C,49,12544) fp32 = 630 MB writes.
// FINAL (v8; 88.128us reproduced R8/R10/R12/R13): HBM-write-roofline kernel,
// ~7.15 TB/s effective (~89% of spec). Axis-by-axis measured optimum:
//  - fine-wave: block = (plane, kh, chunk); 25088 blocks @ occ 9 (conc 1332)
//    -> 99.1% wave efficiency (R8 structural win; coarse grids lost ~25% to
//    tail quantization; residual tail is CLC-work-stolen, irreducible)
//  - TPB=224: 7 row-aligned warps (512B store wavefronts), 63/64 warps/SM;
//    only TPB that tiles the 3136-float4 plane into integer row-aligned warps
//  - per thread: 1 ctr LDG.128 + 3 neighbor LDG.128 spanning [w4-4, w4+8);
//    reflect edge fixups are pure register moves (values already resident)
//  - 7x STG.128 __stcs: policy ordering measured cs(88.1) < wt(96.3) ~ wb(96.4)
//    -> evict-first keeps L2 write-combining, minimizes dirty-line residency
// Compute pipes <9%, issue 14%: gap to spec is DRAM write-turnaround/refresh,
// not SM-addressable. Search closed; all axes swept with measured optima.

#define H 112
#define W 112
#define KS 7
#define PADV 3
#define HW (H * W)            // 12544
#define CC 64
#define NN 4
#define W4N 28                // float4s per row
#define TPB 224               // 7 warps; 224 float4s/block; 14 chunks/plane

__device__ __forceinline__ int reflect_h(int j) {
    j = j < 0 ? -j : j;
    j = j >= H ? (2 * (H - 1) - j) : j;
    return j;
}

__global__ void __launch_bounds__(TPB, 9) san_sub_kernel(
    const float* __restrict__ x, float* __restrict__ out)
{
    const int i  = blockIdx.x * TPB + threadIdx.x;   // float4 index in plane
    const int kh = blockIdx.y;                       // 0..6
    const int plane = blockIdx.z;                    // n*64 + c, 0..255
    const int h  = i / W4N;
    const int w4 = (i - h * W4N) << 2;               // 0,4,...,108

    const bool pL = (w4 != 0);
    const bool pR = (w4 != W - 4);

    const float* xp = x + (size_t)plane * HW;
    float* op = out + ((size_t)plane * (KS * KS) + kh * KS) * HW + ((size_t)i << 2);

    const float4 ctr = *reinterpret_cast<const float4*>(xp + ((size_t)i << 2));

    const int rh = reflect_h(h + kh - PADV);
    const float* row = xp + rh * W;

    // v[j] = x[row, w4-4+j], j=0..11 (interior); edges fixed by reg moves
    float v[12];
    if (pL) *reinterpret_cast<float4*>(&v[0]) =
                *reinterpret_cast<const float4*>(row + w4 - 4);
    *reinterpret_cast<float4*>(&v[4]) =
                *reinterpret_cast<const float4*>(row + w4);
    if (pR) *reinterpret_cast<float4*>(&v[8]) =
                *reinterpret_cast<const float4*>(row + w4 + 4);
    if (!pL) {            // w4==0: x[-3,-2,-1] -> x[3,2,1]
        v[1] = v[7]; v[2] = v[6]; v[3] = v[5];
    }
    if (!pR) {            // w4==108: x[112,113,114] -> x[110,109,108]
        v[8] = v[6]; v[9] = v[5]; v[10] = v[4];
    }

    #pragma unroll
    for (int kw = 0; kw < KS; ++kw) {
        float4 o;
        o.x = ctr.x - v[kw + 1];
        o.y = ctr.y - v[kw + 2];
        o.z = ctr.z - v[kw + 3];
        o.w = ctr.w - v[kw + 4];
        __stcs(reinterpret_cast<float4*>(op + (size_t)kw * HW), o);
    }
}

extern "C" void kernel_launch(void* const* d_in, const int* in_sizes, int n_in,
                              void* d_out, int out_size) {
    const float* x = (const float*)d_in[0];
    float* out = (float*)d_out;
    dim3 block(TPB, 1, 1);
    dim3 grid(HW / 4 / TPB, KS, CC * NN);   // (14, 7, 256) = 25088 blocks
    san_sub_kernel<<<grid, block>>>(x, out);
}

// round 15
// speedup vs baseline: 1.0022x; 1.0022x over previous
#include <cuda_runtime.h>
#include <cuda_bf16.h>

// SAN Subtraction: out[n,c,kk,p] = x[n,c,h,w] - reflectpad(x)[n,c,h+kh,w+kw]
// N=4, C=64, H=W=112, K=7, PAD=3, reflect. out (N,C,49,12544) fp32 = 630 MB writes.
// FINAL (v8; 88.1-88.3us reproduced R8/R10/R12/R13/R14): HBM-write-roofline
// kernel, ~7.15 TB/s effective (~89% of aggregate spec). Measured optima:
//  - fine-wave: block = (plane, kh, chunk); 25088 blocks @ occ 9 (conc 1332)
//    -> 99.1% wave efficiency (R8 structural win: coarse grids lost ~25% to
//    tail quantization)
//  - TPB=224: 7 row-aligned warps (512B store wavefronts), 63/64 warps/SM;
//    only TPB tiling the 3136-float4 plane into integer row-aligned warps
//  - per thread: 1 ctr LDG.128 + 3 neighbor LDG.128 spanning [w4-4, w4+8);
//    reflect edge fixups are pure register moves (values already resident)
//  - 7x STG.128 __stcs: policy ordering cs(88.1) < wt(96.3) ~ wb(96.4) ->
//    evict-first keeps L2 write-combining, minimizes dirty-line residency
// Ruled out by measurement or mechanism: stream order, 256b stores, TMA
// stores (LTS path-independent), L1 pressure, occupancy variants, wt/wb.
// Compute pipes <9%, issue 14%: remaining gap is DRAM write-turnaround.

#define H 112
#define W 112
#define KS 7
#define PADV 3
#define HW (H * W)            // 12544
#define CC 64
#define NN 4
#define W4N 28                // float4s per row
#define TPB 224               // 7 warps; 224 float4s/block; 14 chunks/plane

__device__ __forceinline__ int reflect_h(int j) {
    j = j < 0 ? -j : j;
    j = j >= H ? (2 * (H - 1) - j) : j;
    return j;
}

__global__ void __launch_bounds__(TPB, 9) san_sub_kernel(
    const float* __restrict__ x, float* __restrict__ out)
{
    const int i  = blockIdx.x * TPB + threadIdx.x;   // float4 index in plane
    const int kh = blockIdx.y;                       // 0..6
    const int plane = blockIdx.z;                    // n*64 + c, 0..255
    const int h  = i / W4N;
    const int w4 = (i - h * W4N) << 2;               // 0,4,...,108

    const bool pL = (w4 != 0);
    const bool pR = (w4 != W - 4);

    const float* xp = x + (size_t)plane * HW;
    float* op = out + ((size_t)plane * (KS * KS) + kh * KS) * HW + ((size_t)i << 2);

    const float4 ctr = *reinterpret_cast<const float4*>(xp + ((size_t)i << 2));

    const int rh = reflect_h(h + kh - PADV);
    const float* row = xp + rh * W;

    // v[j] = x[row, w4-4+j], j=0..11 (interior); edges fixed by reg moves
    float v[12];
    if (pL) *reinterpret_cast<float4*>(&v[0]) =
                *reinterpret_cast<const float4*>(row + w4 - 4);
    *reinterpret_cast<float4*>(&v[4]) =
                *reinterpret_cast<const float4*>(row + w4);
    if (pR) *reinterpret_cast<float4*>(&v[8]) =
                *reinterpret_cast<const float4*>(row + w4 + 4);
    if (!pL) {            // w4==0: x[-3,-2,-1] -> x[3,2,1]
        v[1] = v[7]; v[2] = v[6]; v[3] = v[5];
    }
    if (!pR) {            // w4==108: x[112,113,114] -> x[110,109,108]
        v[8] = v[6]; v[9] = v[5]; v[10] = v[4];
    }

    #pragma unroll
    for (int kw = 0; kw < KS; ++kw) {
        float4 o;
        o.x = ctr.x - v[kw + 1];
        o.y = ctr.y - v[kw + 2];
        o.z = ctr.z - v[kw + 3];
        o.w = ctr.w - v[kw + 4];
        __stcs(reinterpret_cast<float4*>(op + (size_t)kw * HW), o);
    }
}

extern "C" void kernel_launch(void* const* d_in, const int* in_sizes, int n_in,
                              void* d_out, int out_size) {
    const float* x = (const float*)d_in[0];
    float* out = (float*)d_out;
    dim3 block(TPB, 1, 1);
    dim3 grid(HW / 4 / TPB, KS, CC * NN);   // (14, 7, 256) = 25088 blocks
    san_sub_kernel<<<grid, block>>>(x, out);
}

// round 16
// speedup vs baseline: 1.0069x; 1.0047x over previous
#include <cuda_runtime.h>
#include <cuda_bf16.h>

// SAN Subtraction: out[n,c,kk,p] = x[n,c,h,w] - reflectpad(x)[n,c,h+kh,w+kw]
// N=4, C=64, H=W=112, K=7, PAD=3, reflect. out (N,C,49,12544) fp32 = 630 MB writes.
// FINAL (v8; 88.10-88.29us reproduced 6x: R8/R10/R12/R13/R14/R15).
// HBM-write-roofline kernel, ~7.15 TB/s effective (~89% of aggregate spec).
// Measured optima per axis:
//  - fine-wave: block = (plane, kh, chunk); 25088 blocks @ occ 9 (conc 1332)
//    -> 18.83 -> 19 waves = 99.1% wave efficiency (R8 structural win: coarse
//    grids lost ~25% to tail quantization)
//  - TPB=224: 7 row-aligned warps (512B store wavefronts), 63/64 warps/SM;
//    only TPB tiling the 3136-float4 plane into integer row-aligned warps
//  - per thread: 1 ctr LDG.128 + 3 neighbor LDG.128 spanning [w4-4, w4+8);
//    reflect edge fixups are pure register moves (values already resident)
//  - 7x STG.128 __stcs: policy ordering cs(88.1) < wt(96.3) ~ wb(96.4) ->
//    evict-first keeps L2 write-combining, minimizes dirty-line residency
// Ruled out by measurement or mechanism: stream orders, 256b stores (neutral
// in R5; breaks wave parity in fine-wave regime), TMA stores (LTS cap is
// path-independent), L1 load pressure, occ 6/8, wt/wb policies.
// Compute pipes <9%, issue 14%: remaining gap to spec is DRAM write-
// turnaround/refresh, not SM-addressable.

#define H 112
#define W 112
#define KS 7
#define PADV 3
#define HW (H * W)            // 12544
#define CC 64
#define NN 4
#define W4N 28                // float4s per row
#define TPB 224               // 7 warps; 224 float4s/block; 14 chunks/plane

__device__ __forceinline__ int reflect_h(int j) {
    j = j < 0 ? -j : j;
    j = j >= H ? (2 * (H - 1) - j) : j;
    return j;
}

__global__ void __launch_bounds__(TPB, 9) san_sub_kernel(
    const float* __restrict__ x, float* __restrict__ out)
{
    const int i  = blockIdx.x * TPB + threadIdx.x;   // float4 index in plane
    const int kh = blockIdx.y;                       // 0..6
    const int plane = blockIdx.z;                    // n*64 + c, 0..255
    const int h  = i / W4N;
    const int w4 = (i - h * W4N) << 2;               // 0,4,...,108

    const bool pL = (w4 != 0);
    const bool pR = (w4 != W - 4);

    const float* xp = x + (size_t)plane * HW;
    float* op = out + ((size_t)plane * (KS * KS) + kh * KS) * HW + ((size_t)i << 2);

    const float4 ctr = *reinterpret_cast<const float4*>(xp + ((size_t)i << 2));

    const int rh = reflect_h(h + kh - PADV);
    const float* row = xp + rh * W;

    // v[j] = x[row, w4-4+j], j=0..11 (interior); edges fixed by reg moves
    float v[12];
    if (pL) *reinterpret_cast<float4*>(&v[0]) =
                *reinterpret_cast<const float4*>(row + w4 - 4);
    *reinterpret_cast<float4*>(&v[4]) =
                *reinterpret_cast<const float4*>(row + w4);
    if (pR) *reinterpret_cast<float4*>(&v[8]) =
                *reinterpret_cast<const float4*>(row + w4 + 4);
    if (!pL) {            // w4==0: x[-3,-2,-1] -> x[3,2,1]
        v[1] = v[7]; v[2] = v[6]; v[3] = v[5];
    }
    if (!pR) {            // w4==108: x[112,113,114] -> x[110,109,108]
        v[8] = v[6]; v[9] = v[5]; v[10] = v[4];
    }

    #pragma unroll
    for (int kw = 0; kw < KS; ++kw) {
        float4 o;
        o.x = ctr.x - v[kw + 1];
        o.y = ctr.y - v[kw + 2];
        o.z = ctr.z - v[kw + 3];
        o.w = ctr.w - v[kw + 4];
        __stcs(reinterpret_cast<float4*>(op + (size_t)kw * HW), o);
    }
}

extern "C" void kernel_launch(void* const* d_in, const int* in_sizes, int n_in,
                              void* d_out, int out_size) {
    const float* x = (const float*)d_in[0];
    float* out = (float*)d_out;
    dim3 block(TPB, 1, 1);
    dim3 grid(HW / 4 / TPB, KS, CC * NN);   // (14, 7, 256) = 25088 blocks
    san_sub_kernel<<<grid, block>>>(x, out);
}